// round 14
// baseline (speedup 1.0000x reference)
#include <cuda_runtime.h>
#include <stdint.h>

#define BB   8
#define NN   4096
#define CPN  57
#define KK   16
#define THR  0.04f
#define GD   10          // cells per dim
#define NC2  1000        // GD^3
#define NBIN 64
#define THCAP 10         // per-thread threshold-list slots (2 threads/point)

// ---------------- scratch (device globals; no allocation allowed) -----------
__device__ int2   g_knn_pair[BB * NN * KK];   // (idx, dist bits) interleaved
__device__ int    g_off[BB * 1024];
__device__ float4 g_sx[BB * NN];
__device__ int    g_sj[BB * NN];
__device__ float  g_h67[BB * NN * 68];        // [agg(64) | xyz(3) | pad]

// ---------------------------------------------------------------------------
// f32x2 packed helpers
// ---------------------------------------------------------------------------
typedef unsigned long long u64;
__device__ __forceinline__ u64 f2pack(float a, float b) {
    u64 r; asm("mov.b64 %0,{%1,%2};" : "=l"(r) : "f"(a), "f"(b)); return r;
}
__device__ __forceinline__ void f2unpack(u64 v, float& a, float& b) {
    asm("mov.b64 {%0,%1},%2;" : "=f"(a), "=f"(b) : "l"(v));
}
__device__ __forceinline__ u64 ffma2(u64 a, u64 b, u64 c) {
    u64 d; asm("fma.rn.f32x2 %0,%1,%2,%3;" : "=l"(d) : "l"(a), "l"(b), "l"(c));
    return d;
}
__device__ __forceinline__ void lds2x64(u64& a, u64& b, unsigned addr) {
    asm volatile("ld.shared.v2.b64 {%0,%1},[%2];"
                 : "=l"(a), "=l"(b) : "r"(addr));
}

// ---------------------------------------------------------------------------
// Fused grid build: one block per batch, 10^3 cells (cell = radius/2 = 0.1).
// ---------------------------------------------------------------------------
__device__ __forceinline__ int cell_of(float x, float y, float z) {
    int cx = min((int)(x * 10.0f), GD - 1);
    int cy = min((int)(y * 10.0f), GD - 1);
    int cz = min((int)(z * 10.0f), GD - 1);
    return (cx * GD + cy) * GD + cz;
}

__global__ void grid_build(const float* __restrict__ xyz) {
    __shared__ int scnt[1024];
    __shared__ int ssum[512];
    __shared__ int soff[1024 + 1];
    __shared__ int scur[1024];
    const int tid = threadIdx.x;
    const int b = blockIdx.x;
    const float* bx = xyz + (size_t)b * NN * 3;

    scnt[tid] = 0; scnt[tid + 512] = 0;
    __syncthreads();

    for (int i = tid; i < NN; i += 512) {
        float x = bx[i * 3 + 0], y = bx[i * 3 + 1], z = bx[i * 3 + 2];
        atomicAdd(&scnt[cell_of(x, y, z)], 1);
    }
    __syncthreads();

    const int c0v = scnt[2 * tid];
    const int c1v = scnt[2 * tid + 1];
    ssum[tid] = c0v + c1v;
    __syncthreads();
#pragma unroll
    for (int d = 1; d < 512; d <<= 1) {
        int v = ssum[tid];
        int u = (tid >= d) ? ssum[tid - d] : 0;
        __syncthreads();
        ssum[tid] = v + u;
        __syncthreads();
    }
    const int excl = (tid == 0) ? 0 : ssum[tid - 1];
    soff[2 * tid]     = excl;
    soff[2 * tid + 1] = excl + c0v;
    scur[2 * tid]     = excl;
    scur[2 * tid + 1] = excl + c0v;
    if (tid == 511) soff[1024] = ssum[511];
    __syncthreads();

    for (int t = tid; t <= NC2; t += 512) g_off[b * 1024 + t] = soff[t];

    for (int i = tid; i < NN; i += 512) {
        float x = bx[i * 3 + 0], y = bx[i * 3 + 1], z = bx[i * 3 + 2];
        int cell = cell_of(x, y, z);
        int pos = atomicAdd(&scur[cell], 1);
        float sq = fmaf(z, z, fmaf(y, y, x * x));
        g_sx[(b << 12) + pos] = make_float4(x, y, z, sq);
        g_sj[(b << 12) + pos] = i;
    }
}

// ---------------------------------------------------------------------------
// kNN query: TWO threads per point (13/12 cell-column split, deterministic
// histogram-based merge).  Unchanged from R13.
// ---------------------------------------------------------------------------
#define KNN_SCAN2(MLO, MHI, BODY)                                             \
    for (int m = (MLO); m < (MHI); m++) {                                     \
        const int dx = m / 5 - 2, dy = m % 5 - 2;                             \
        int ncx = cx + dx; if (ncx < 0 || ncx > GD - 1) continue;             \
        int ncy = cy + dy; if (ncy < 0 || ncy > GD - 1) continue;             \
        int cb2 = b * 1024 + (ncx * GD + ncy) * GD;                           \
        int sbeg = g_off[cb2 + czlo];                                         \
        int send = g_off[cb2 + czhi + 1];                                     \
        for (int s = sbeg; s < send; s++) {                                   \
            float4 c = g_sx[(b << 12) + s];                                   \
            float dot = fmaf(q.z, c.z, fmaf(q.y, c.y, q.x * c.x));            \
            float rhs = fmaf(0.5f, c.w, qoff);                                \
            if (dot >= rhs) {                                                 \
                float t1 = qsq + c.w;                                         \
                float d = __fsub_rn(t1, __fmul_rn(2.0f, dot));                \
                if (d <= THR) { BODY }                                        \
            }                                                                 \
        }                                                                     \
    }

__global__ __launch_bounds__(128) void knn_query() {
    __shared__ unsigned short hist[NBIN * 128];
    __shared__ int2 tl[64 * 2 * THCAP];
    const int tid  = threadIdx.x;
    const int pt   = tid >> 1;
    const int half = tid & 1;
    const int b    = blockIdx.y;
    const int slot = blockIdx.x * 64 + pt;
    const float4 q = g_sx[(b << 12) + slot];
    const int qi   = g_sj[(b << 12) + slot];
    const float qsq = q.w;
    const int cx = min((int)(q.x * 10.0f), GD - 1);
    const int cy = min((int)(q.y * 10.0f), GD - 1);
    const int cz = min((int)(q.z * 10.0f), GD - 1);
    const float qoff = 0.5f * (qsq - THR) - 1e-5f;
    const int czlo = max(cz - 2, 0), czhi = min(cz + 2, GD - 1);
    const int mlo = half ? 13 : 0, mhi = half ? 25 : 13;

#pragma unroll 8
    for (int bn = 0; bn < NBIN; bn++) hist[bn * 128 + tid] = 0;

    KNN_SCAN2(mlo, mhi, {
        int bn = max(0, min(NBIN - 1, (int)(d * 1600.0f)));   // 64 / 0.04
        hist[bn * 128 + tid]++;
    })
    __syncwarp();

    const int col0 = tid & ~1, col1 = col0 + 1;
    int tstar = NBIN, cum = 0, nd0 = 0, ndt = 0;
#pragma unroll 8
    for (int bn = 0; bn < NBIN; bn++) {
        int h0 = (int)hist[bn * 128 + col0];
        int h1 = (int)hist[bn * 128 + col1];
        int c = h0 + h1;
        if (tstar == NBIN && cum + c >= KK) tstar = bn;
        if (tstar == NBIN) { nd0 += h0; ndt += c; }
        cum += c;
    }

    const int base = (b * NN + qi) * KK;
    const int mybase = half ? nd0 : 0;
    int cnt = 0, tcnt = 0;

    KNN_SCAN2(mlo, mhi, {
        int bn = max(0, min(NBIN - 1, (int)(d * 1600.0f)));
        if (bn < tstar) {
            int j = g_sj[(b << 12) + s];
            g_knn_pair[base + mybase + cnt] =
                make_int2(j, __float_as_int(fmaxf(d, 0.0f)));
            cnt++;
        } else if (bn == tstar && tcnt < THCAP) {
            int j = g_sj[(b << 12) + s];
            tl[(pt * 2 + half) * THCAP + tcnt] = make_int2(j, __float_as_int(d));
            tcnt++;
        }
    })
    __syncwarp();

    if (half == 0) {
        int wcnt = ndt;
        if (tstar < NBIN) {
            const int tc0 = min((int)hist[tstar * 128 + col0], THCAP);
            const int tc1 = min((int)hist[tstar * 128 + col1], THCAP);
            int need = KK - ndt;
            const int tot = tc0 + tc1;
            if (need > tot) need = tot;
            const int tb = pt * 2 * THCAP;
            for (int s2 = 0; s2 < need; s2++) {
                float bd = 3.0e38f; int bj = 0x7fffffff, bi = -1;
                for (int i2 = 0; i2 < tc0; i2++) {
                    int2 e = tl[tb + i2];
                    float dv = __int_as_float(e.y);
                    bool g = (dv < bd) || (dv == bd && e.x < bj);
                    if (g) { bd = dv; bj = e.x; bi = tb + i2; }
                }
                for (int i2 = 0; i2 < tc1; i2++) {
                    int2 e = tl[tb + THCAP + i2];
                    float dv = __int_as_float(e.y);
                    bool g = (dv < bd) || (dv == bd && e.x < bj);
                    if (g) { bd = dv; bj = e.x; bi = tb + THCAP + i2; }
                }
                tl[bi].y = __float_as_int(3.0e38f);
                g_knn_pair[base + wcnt] =
                    make_int2(bj, __float_as_int(fmaxf(bd, 0.0f)));
                wcnt++;
            }
        }
        for (; wcnt < KK; wcnt++) g_knn_pair[base + wcnt] = make_int2(qi, 0);
    }
}

// ============================================================================
// dfg kernel v3: 8 blocks/SM (32 warps).  Weights via __ldg (L1), SMEM =
// scratch only (20.7KB/block).  dfg2 runs as TWO 8-k half-passes over the
// same 16-k hidT tile: accumulators halve to 16 regs, each pass aggregates
// its 8 ks immediately (k ascending -> summation order bit-identical).
// __launch_bounds__(128, 8) caps at 64 regs.
// ============================================================================
#define DW       4
#define DTPB     (DW * 32)
#define DBLOCKS  (8 * 148)           // 1184
#define DWARPS   (DBLOCKS * DW)      // 4736
#define D_WS     1296
#define DSMEM_BYTES (DW * D_WS * 4)

__global__ __launch_bounds__(DTPB, 8)
void dfg_kernel(const float* __restrict__ xyz,
                const float* __restrict__ points,
                const float* __restrict__ w1, const float* __restrict__ b1,
                const float* __restrict__ w2, const float* __restrict__ b2) {
    extern __shared__ float sm[];

    const int warp = threadIdx.x >> 5;
    const int lane = threadIdx.x & 31;
    const int c0 = 2 * lane, c1 = c0 + 1;

    float w1r0[7], w1r1[7];
#pragma unroll
    for (int t = 0; t < 7; t++) {
        w1r0[t] = __ldg(w1 + t * 64 + c0);
        w1r1[t] = __ldg(w1 + t * 64 + c1);
    }
    const float lb10 = __ldg(b1 + c0), lb11 = __ldg(b1 + c1);
    const float lb20 = __ldg(b2 + c0), lb21 = __ldg(b2 + c1);

    float* ws = sm + warp * D_WS;
    const unsigned hidT32 =
        (unsigned)__cvta_generic_to_shared(sm) + (unsigned)(warp * D_WS) * 4u;

    const int gwarp = blockIdx.x * DW + warp;

#pragma unroll 1
    for (int p = gwarp; p < BB * NN; p += DWARPS) {
        const int b = p >> 12;
        const float qx = xyz[p * 3 + 0];
        const float qy = xyz[p * 3 + 1];
        const float qz = xyz[p * 3 + 2];
        const int2* kp = g_knn_pair + (size_t)p * KK;

        // ---- dfg layer 1: 4 k at a time, swizzled transpose store -------
        const int sA = (c0 >> 3) & 3;
#pragma unroll
        for (int kb = 0; kb < 4; kb++) {
            float2 hk[4];
#pragma unroll
            for (int kk = 0; kk < 4; kk++) {
                const int2 pr = kp[kb * 4 + kk];     // uniform broadcast LDG
                const int   j  = pr.x;
                const float dk = __int_as_float(pr.y);
                const float* nb = xyz + ((size_t)(b << 12) + j) * 3;
                const float g0 = nb[0], g1 = nb[1], g2 = nb[2];
                const float g3 = g0 - qx, g4 = g1 - qy, g5 = g2 - qz;
                float h0 = lb10, h1 = lb11;
                h0 = fmaf(g0, w1r0[0], h0); h1 = fmaf(g0, w1r1[0], h1);
                h0 = fmaf(g1, w1r0[1], h0); h1 = fmaf(g1, w1r1[1], h1);
                h0 = fmaf(g2, w1r0[2], h0); h1 = fmaf(g2, w1r1[2], h1);
                h0 = fmaf(g3, w1r0[3], h0); h1 = fmaf(g3, w1r1[3], h1);
                h0 = fmaf(g4, w1r0[4], h0); h1 = fmaf(g4, w1r1[4], h1);
                h0 = fmaf(g5, w1r0[5], h0); h1 = fmaf(g5, w1r1[5], h1);
                h0 = fmaf(dk, w1r0[6], h0); h1 = fmaf(dk, w1r1[6], h1);
                hk[kk] = make_float2(fmaxf(h0, 0.0f), fmaxf(h1, 0.0f));
            }
            const int slot = (kb ^ sA) << 2;
            *(float4*)(ws + c0 * 20 + slot) =
                make_float4(hk[0].x, hk[1].x, hk[2].x, hk[3].x);
            *(float4*)(ws + c1 * 20 + slot) =
                make_float4(hk[0].y, hk[1].y, hk[2].y, hk[3].y);
        }
        __syncwarp();

        // ---- dfg layer 2 + aggregation: two 8-k half-passes -------------
        float agg0 = 0.0f, agg1 = 0.0f;
#pragma unroll
        for (int ph = 0; ph < 2; ph++) {
            u64 a0[4], a1[4];
            {
                const u64 bb0 = f2pack(lb20, lb20);
                const u64 bb1 = f2pack(lb21, lb21);
#pragma unroll
                for (int m = 0; m < 4; m++) { a0[m] = bb0; a1[m] = bb1; }
            }
#pragma unroll
            for (int o = 0; o < 8; o++) {
#pragma unroll
                for (int tt = 0; tt < 8; tt++) {
                    const int t = o * 8 + tt;
                    const int sw = (t >> 3) & 3;
                    const float2 w = __ldg((const float2*)(w2 + t * 64 + c0));
                    const u64 w00 = f2pack(w.x, w.x);
                    const u64 w11 = f2pack(w.y, w.y);
                    const unsigned rowa = hidT32 + (unsigned)(t * 20) * 4u;
#pragma unroll
                    for (int g2 = 0; g2 < 2; g2++) {
                        const int g = ph * 2 + g2;
                        u64 h01, h23;
                        lds2x64(h01, h23,
                                rowa + (unsigned)(((g ^ sw) << 2) * 4));
                        const int m = g2 << 1;
                        a0[m]     = ffma2(h01, w00, a0[m]);
                        a0[m + 1] = ffma2(h23, w00, a0[m + 1]);
                        a1[m]     = ffma2(h01, w11, a1[m]);
                        a1[m + 1] = ffma2(h23, w11, a1[m + 1]);
                    }
                }
            }
            // aggregate this pass's 8 ks (k ascending overall)
#pragma unroll
            for (int m = 0; m < 4; m++) {
                float oE0, oO0, oE1, oO1;
                f2unpack(a0[m], oE0, oO0);
                f2unpack(a1[m], oE1, oO1);
#pragma unroll
                for (int kk = 0; kk < 2; kk++) {
                    const int k = ph * 8 + 2 * m + kk;
                    const float o0 = kk ? oO0 : oE0;
                    const float o1 = kk ? oO1 : oE1;
                    const int2 pr = kp[k];               // L1-hit broadcast
                    const int   j  = pr.x;
                    const float dk = __int_as_float(pr.y);
                    const float* nb = xyz + ((size_t)(b << 12) + j) * 3;
                    const float g0 = nb[0], g1 = nb[1], g2 = nb[2];
                    const float* prow = points + ((size_t)(b << 12) + j) * CPN;
                    float gp0 = (c0 >= 7) ? prow[c0 - 7] : 0.0f;
                    float gp1 = (c1 >= 7) ? prow[c1 - 7] : 0.0f;
                    if (lane == 0)      { gp0 = g0; gp1 = g1; }
                    else if (lane == 1) { gp0 = g2; gp1 = g0 - qx; }
                    else if (lane == 2) { gp0 = g1 - qy; gp1 = g2 - qz; }
                    else if (lane == 3) { gp0 = dk; }
                    agg0 = fmaf(o0, gp0, agg0);
                    agg1 = fmaf(o1, gp1, agg1);
                }
            }
        }
        agg0 *= 0.0625f; agg1 *= 0.0625f;

        float* hb = g_h67 + (size_t)p * 68;
        *(float2*)&hb[c0] = make_float2(agg0, agg1);
        if (lane == 0) { hb[64] = qx; hb[65] = qy; hb[66] = qz; }
        __syncwarp();
    }
}

// ============================================================================
// mlp kernel: PERSISTENT grid-stride (exact R12/R13 config).
// ============================================================================
#define MW       8
#define MPPW     4
#define MTPB     (MW * 32)
#define MBLOCKS  592
#define MWARPS   (MBLOCKS * MW)      // 4736
#define MGROUPS  (BB * NN / MPPW)    // 8192
#define M_WS     800
#define MSMEM_BYTES  (MW * M_WS * 4)

__global__ __launch_bounds__(MTPB)
void mlp_kernel(const float* __restrict__ points,
                const float* __restrict__ m1, const float* __restrict__ mb1,
                const float* __restrict__ m2, const float* __restrict__ mb2,
                const float* __restrict__ sc, const float* __restrict__ scb,
                float* __restrict__ out) {
    extern __shared__ float sm[];

    const int warp = threadIdx.x >> 5;
    const int lane = threadIdx.x & 31;
    const int c0 = 2 * lane;
    const int c4 = 4 * lane;

    float* h67b  = sm + warp * M_WS;   // 4 x 68, later reused as prow
    float* h128b = h67b + 272;         // 4 x 128

    const int gwarp = blockIdx.x * MW + warp;

#pragma unroll 1
    for (int grp = gwarp; grp < MGROUPS; grp += MWARPS) {
        const int pbase = grp * MPPW;

#pragma unroll
        for (int pp = 0; pp < MPPW; pp++) {
            const float* src = g_h67 + (size_t)(pbase + pp) * 68;
            for (int t = lane; t < 68; t += 32) h67b[pp * 68 + t] = src[t];
        }
        __syncwarp();

        // mlp1: [67] -> [128], relu.  input order = [xyz(3), agg(64)]
        {
            float a0[MPPW], a1[MPPW], a2[MPPW], a3[MPPW];
            const float4 bbv = __ldg((const float4*)(mb1 + c4));
#pragma unroll
            for (int pp = 0; pp < MPPW; pp++) {
                a0[pp] = bbv.x; a1[pp] = bbv.y; a2[pp] = bbv.z; a3[pp] = bbv.w;
            }

#pragma unroll
            for (int t = 0; t < 3; t++) {          // xyz rows
                const float4 w = __ldg((const float4*)(m1 + t * 128 + c4));
#pragma unroll
                for (int pp = 0; pp < MPPW; pp++) {
                    const float v = h67b[pp * 68 + 64 + t];
                    a0[pp] = fmaf(v, w.x, a0[pp]);
                    a1[pp] = fmaf(v, w.y, a1[pp]);
                    a2[pp] = fmaf(v, w.z, a2[pp]);
                    a3[pp] = fmaf(v, w.w, a3[pp]);
                }
            }
#pragma unroll 4
            for (int i = 0; i < 64; i++) {         // agg rows
                const float4 w = __ldg((const float4*)(m1 + (3 + i) * 128 + c4));
#pragma unroll
                for (int pp = 0; pp < MPPW; pp++) {
                    const float v = h67b[pp * 68 + i];
                    a0[pp] = fmaf(v, w.x, a0[pp]);
                    a1[pp] = fmaf(v, w.y, a1[pp]);
                    a2[pp] = fmaf(v, w.z, a2[pp]);
                    a3[pp] = fmaf(v, w.w, a3[pp]);
                }
            }
            __syncwarp();
#pragma unroll
            for (int pp = 0; pp < MPPW; pp++) {
                *(float4*)&h128b[pp * 128 + c4] =
                    make_float4(fmaxf(a0[pp], 0.0f), fmaxf(a1[pp], 0.0f),
                                fmaxf(a2[pp], 0.0f), fmaxf(a3[pp], 0.0f));
            }
        }
        __syncwarp();

        // reuse h67b as prow staging (mlp1 reads complete)
#pragma unroll
        for (int pp = 0; pp < MPPW; pp++) {
            const float* ps = points + (size_t)(pbase + pp) * CPN;
            for (int t = lane; t < CPN; t += 32) h67b[pp * 68 + t] = ps[t];
        }
        __syncwarp();

        // mlp2: [128] -> [64]
        float om0[MPPW], om1[MPPW];
        {
            const float2 mb = __ldg((const float2*)(mb2 + c0));
#pragma unroll
            for (int pp = 0; pp < MPPW; pp++) { om0[pp] = mb.x; om1[pp] = mb.y; }
#pragma unroll 4
            for (int t = 0; t < 128; t++) {
                const float2 w = __ldg((const float2*)(m2 + t * 64 + c0));
#pragma unroll
                for (int pp = 0; pp < MPPW; pp++) {
                    const float v = h128b[pp * 128 + t];
                    om0[pp] = fmaf(v, w.x, om0[pp]);
                    om1[pp] = fmaf(v, w.y, om1[pp]);
                }
            }
        }

        // shortcut: points @ sc_w + sc_b
        float or0[MPPW], or1[MPPW];
        {
            const float2 sb = __ldg((const float2*)(scb + c0));
#pragma unroll
            for (int pp = 0; pp < MPPW; pp++) { or0[pp] = sb.x; or1[pp] = sb.y; }
#pragma unroll 4
            for (int t = 0; t < CPN; t++) {
                const float2 w = __ldg((const float2*)(sc + t * 64 + c0));
#pragma unroll
                for (int pp = 0; pp < MPPW; pp++) {
                    const float v = h67b[pp * 68 + t];
                    or0[pp] = fmaf(v, w.x, or0[pp]);
                    or1[pp] = fmaf(v, w.y, or1[pp]);
                }
            }
        }

#pragma unroll
        for (int pp = 0; pp < MPPW; pp++) {
            const int p = pbase + pp;
            *(float2*)&out[(size_t)p * 64 + c0] =
                make_float2(fmaxf(or0[pp] + om0[pp], 0.0f),
                            fmaxf(or1[pp] + om1[pp], 0.0f));
        }
        __syncwarp();
    }
}

// ============================================================================
extern "C" void kernel_launch(void* const* d_in, const int* in_sizes, int n_in,
                              void* d_out, int out_size) {
    const float* xyz    = (const float*)d_in[0];
    const float* points = (const float*)d_in[1];
    const float* w1     = (const float*)d_in[2];
    const float* b1     = (const float*)d_in[3];
    const float* w2     = (const float*)d_in[4];
    const float* b2     = (const float*)d_in[5];
    const float* m1     = (const float*)d_in[6];
    const float* mb1    = (const float*)d_in[7];
    const float* m2     = (const float*)d_in[8];
    const float* mb2    = (const float*)d_in[9];
    const float* sc     = (const float*)d_in[10];
    const float* scb    = (const float*)d_in[11];
    float* out = (float*)d_out;
    (void)in_sizes; (void)n_in; (void)out_size;

    grid_build<<<BB, 512>>>(xyz);
    knn_query<<<dim3(NN / 64, BB), 128>>>();

    cudaFuncSetAttribute(dfg_kernel,
                         cudaFuncAttributeMaxDynamicSharedMemorySize,
                         DSMEM_BYTES);
    dfg_kernel<<<DBLOCKS, DTPB, DSMEM_BYTES>>>(
        xyz, points, w1, b1, w2, b2);

    cudaFuncSetAttribute(mlp_kernel,
                         cudaFuncAttributeMaxDynamicSharedMemorySize,
                         MSMEM_BYTES);
    mlp_kernel<<<MBLOCKS, MTPB, MSMEM_BYTES>>>(
        points, m1, mb1, m2, mb2, sc, scb, out);
}

// round 15
// speedup vs baseline: 1.1854x; 1.1854x over previous
#include <cuda_runtime.h>
#include <stdint.h>

#define BB   8
#define NN   4096
#define CPN  57
#define KK   16
#define THR  0.04f
#define GD   10          // cells per dim
#define NC2  1000        // GD^3
#define NBIN 64
#define THCAP 10         // per-thread threshold-list slots (2 threads/point)

// ---------------- scratch (device globals; no allocation allowed) -----------
__device__ int2   g_knn_pair[BB * NN * KK];   // (idx, dist bits) interleaved
__device__ int    g_off[BB * 1024];
__device__ float4 g_sx[BB * NN];
__device__ int    g_sj[BB * NN];
__device__ float  g_h67[BB * NN * 68];        // [agg(64) | xyz(3) | pad]

// ---------------------------------------------------------------------------
// f32x2 packed helpers
// ---------------------------------------------------------------------------
typedef unsigned long long u64;
__device__ __forceinline__ u64 f2pack(float a, float b) {
    u64 r; asm("mov.b64 %0,{%1,%2};" : "=l"(r) : "f"(a), "f"(b)); return r;
}
__device__ __forceinline__ void f2unpack(u64 v, float& a, float& b) {
    asm("mov.b64 {%0,%1},%2;" : "=f"(a), "=f"(b) : "l"(v));
}
__device__ __forceinline__ u64 ffma2(u64 a, u64 b, u64 c) {
    u64 d; asm("fma.rn.f32x2 %0,%1,%2,%3;" : "=l"(d) : "l"(a), "l"(b), "l"(c));
    return d;
}
__device__ __forceinline__ void lds2x64(u64& a, u64& b, unsigned addr) {
    asm volatile("ld.shared.v2.b64 {%0,%1},[%2];"
                 : "=l"(a), "=l"(b) : "r"(addr));
}

// ---------------------------------------------------------------------------
// Fused grid build: one block per batch, 10^3 cells (cell = radius/2 = 0.1).
// ---------------------------------------------------------------------------
__device__ __forceinline__ int cell_of(float x, float y, float z) {
    int cx = min((int)(x * 10.0f), GD - 1);
    int cy = min((int)(y * 10.0f), GD - 1);
    int cz = min((int)(z * 10.0f), GD - 1);
    return (cx * GD + cy) * GD + cz;
}

__global__ void grid_build(const float* __restrict__ xyz) {
    __shared__ int scnt[1024];
    __shared__ int ssum[512];
    __shared__ int soff[1024 + 1];
    __shared__ int scur[1024];
    const int tid = threadIdx.x;
    const int b = blockIdx.x;
    const float* bx = xyz + (size_t)b * NN * 3;

    scnt[tid] = 0; scnt[tid + 512] = 0;
    __syncthreads();

    for (int i = tid; i < NN; i += 512) {
        float x = bx[i * 3 + 0], y = bx[i * 3 + 1], z = bx[i * 3 + 2];
        atomicAdd(&scnt[cell_of(x, y, z)], 1);
    }
    __syncthreads();

    const int c0v = scnt[2 * tid];
    const int c1v = scnt[2 * tid + 1];
    ssum[tid] = c0v + c1v;
    __syncthreads();
#pragma unroll
    for (int d = 1; d < 512; d <<= 1) {
        int v = ssum[tid];
        int u = (tid >= d) ? ssum[tid - d] : 0;
        __syncthreads();
        ssum[tid] = v + u;
        __syncthreads();
    }
    const int excl = (tid == 0) ? 0 : ssum[tid - 1];
    soff[2 * tid]     = excl;
    soff[2 * tid + 1] = excl + c0v;
    scur[2 * tid]     = excl;
    scur[2 * tid + 1] = excl + c0v;
    if (tid == 511) soff[1024] = ssum[511];
    __syncthreads();

    for (int t = tid; t <= NC2; t += 512) g_off[b * 1024 + t] = soff[t];

    for (int i = tid; i < NN; i += 512) {
        float x = bx[i * 3 + 0], y = bx[i * 3 + 1], z = bx[i * 3 + 2];
        int cell = cell_of(x, y, z);
        int pos = atomicAdd(&scur[cell], 1);
        float sq = fmaf(z, z, fmaf(y, y, x * x));
        g_sx[(b << 12) + pos] = make_float4(x, y, z, sq);
        g_sj[(b << 12) + pos] = i;
    }
}

// ---------------------------------------------------------------------------
// kNN query: TWO threads per point (13/12 cell-column split, deterministic
// histogram-based merge).  Unchanged from R13.
// ---------------------------------------------------------------------------
#define KNN_SCAN2(MLO, MHI, BODY)                                             \
    for (int m = (MLO); m < (MHI); m++) {                                     \
        const int dx = m / 5 - 2, dy = m % 5 - 2;                             \
        int ncx = cx + dx; if (ncx < 0 || ncx > GD - 1) continue;             \
        int ncy = cy + dy; if (ncy < 0 || ncy > GD - 1) continue;             \
        int cb2 = b * 1024 + (ncx * GD + ncy) * GD;                           \
        int sbeg = g_off[cb2 + czlo];                                         \
        int send = g_off[cb2 + czhi + 1];                                     \
        for (int s = sbeg; s < send; s++) {                                   \
            float4 c = g_sx[(b << 12) + s];                                   \
            float dot = fmaf(q.z, c.z, fmaf(q.y, c.y, q.x * c.x));            \
            float rhs = fmaf(0.5f, c.w, qoff);                                \
            if (dot >= rhs) {                                                 \
                float t1 = qsq + c.w;                                         \
                float d = __fsub_rn(t1, __fmul_rn(2.0f, dot));                \
                if (d <= THR) { BODY }                                        \
            }                                                                 \
        }                                                                     \
    }

__global__ __launch_bounds__(128) void knn_query() {
    __shared__ unsigned short hist[NBIN * 128];
    __shared__ int2 tl[64 * 2 * THCAP];
    const int tid  = threadIdx.x;
    const int pt   = tid >> 1;
    const int half = tid & 1;
    const int b    = blockIdx.y;
    const int slot = blockIdx.x * 64 + pt;
    const float4 q = g_sx[(b << 12) + slot];
    const int qi   = g_sj[(b << 12) + slot];
    const float qsq = q.w;
    const int cx = min((int)(q.x * 10.0f), GD - 1);
    const int cy = min((int)(q.y * 10.0f), GD - 1);
    const int cz = min((int)(q.z * 10.0f), GD - 1);
    const float qoff = 0.5f * (qsq - THR) - 1e-5f;
    const int czlo = max(cz - 2, 0), czhi = min(cz + 2, GD - 1);
    const int mlo = half ? 13 : 0, mhi = half ? 25 : 13;

#pragma unroll 8
    for (int bn = 0; bn < NBIN; bn++) hist[bn * 128 + tid] = 0;

    KNN_SCAN2(mlo, mhi, {
        int bn = max(0, min(NBIN - 1, (int)(d * 1600.0f)));   // 64 / 0.04
        hist[bn * 128 + tid]++;
    })
    __syncwarp();

    const int col0 = tid & ~1, col1 = col0 + 1;
    int tstar = NBIN, cum = 0, nd0 = 0, ndt = 0;
#pragma unroll 8
    for (int bn = 0; bn < NBIN; bn++) {
        int h0 = (int)hist[bn * 128 + col0];
        int h1 = (int)hist[bn * 128 + col1];
        int c = h0 + h1;
        if (tstar == NBIN && cum + c >= KK) tstar = bn;
        if (tstar == NBIN) { nd0 += h0; ndt += c; }
        cum += c;
    }

    const int base = (b * NN + qi) * KK;
    const int mybase = half ? nd0 : 0;
    int cnt = 0, tcnt = 0;

    KNN_SCAN2(mlo, mhi, {
        int bn = max(0, min(NBIN - 1, (int)(d * 1600.0f)));
        if (bn < tstar) {
            int j = g_sj[(b << 12) + s];
            g_knn_pair[base + mybase + cnt] =
                make_int2(j, __float_as_int(fmaxf(d, 0.0f)));
            cnt++;
        } else if (bn == tstar && tcnt < THCAP) {
            int j = g_sj[(b << 12) + s];
            tl[(pt * 2 + half) * THCAP + tcnt] = make_int2(j, __float_as_int(d));
            tcnt++;
        }
    })
    __syncwarp();

    if (half == 0) {
        int wcnt = ndt;
        if (tstar < NBIN) {
            const int tc0 = min((int)hist[tstar * 128 + col0], THCAP);
            const int tc1 = min((int)hist[tstar * 128 + col1], THCAP);
            int need = KK - ndt;
            const int tot = tc0 + tc1;
            if (need > tot) need = tot;
            const int tb = pt * 2 * THCAP;
            for (int s2 = 0; s2 < need; s2++) {
                float bd = 3.0e38f; int bj = 0x7fffffff, bi = -1;
                for (int i2 = 0; i2 < tc0; i2++) {
                    int2 e = tl[tb + i2];
                    float dv = __int_as_float(e.y);
                    bool g = (dv < bd) || (dv == bd && e.x < bj);
                    if (g) { bd = dv; bj = e.x; bi = tb + i2; }
                }
                for (int i2 = 0; i2 < tc1; i2++) {
                    int2 e = tl[tb + THCAP + i2];
                    float dv = __int_as_float(e.y);
                    bool g = (dv < bd) || (dv == bd && e.x < bj);
                    if (g) { bd = dv; bj = e.x; bi = tb + THCAP + i2; }
                }
                tl[bi].y = __float_as_int(3.0e38f);
                g_knn_pair[base + wcnt] =
                    make_int2(bj, __float_as_int(fmaxf(bd, 0.0f)));
                wcnt++;
            }
        }
        for (; wcnt < KK; wcnt++) g_knn_pair[base + wcnt] = make_int2(qi, 0);
    }
}

// ============================================================================
// dfg kernel v4: half-pass accumulators (16 regs) + W2 in SMEM (read twice).
// W1/b1/b2 via __ldg (tiny, loop-invariant).  SMEM/block = 37.4KB ->
// 6 blocks/SM by SMEM; __launch_bounds__(128,6) = 85-reg budget (no hard
// squeeze).  24 warps/SM (vs 20 in R13).  Persistent 888 blocks.
// Summation order bit-identical (validated in R14).
// ============================================================================
#define DW       4
#define DTPB     (DW * 32)
#define DBLOCKS  (6 * 148)           // 888
#define DWARPS   (DBLOCKS * DW)      // 3552
#define D_W2     0
#define D_SCR    4160                // 4096 W2 + 64 pad
#define D_WS     1296
#define DSMEM_FLOATS (D_SCR + DW * D_WS)   // 9344
#define DSMEM_BYTES  (DSMEM_FLOATS * 4)    // 37376

__global__ __launch_bounds__(DTPB, 6)
void dfg_kernel(const float* __restrict__ xyz,
                const float* __restrict__ points,
                const float* __restrict__ w1, const float* __restrict__ b1,
                const float* __restrict__ w2, const float* __restrict__ b2) {
    extern __shared__ float sm[];

    for (int t = threadIdx.x; t < 4096; t += DTPB) sm[D_W2 + t] = w2[t];
    __syncthreads();

    const int warp = threadIdx.x >> 5;
    const int lane = threadIdx.x & 31;
    const int c0 = 2 * lane, c1 = c0 + 1;

    float w1r0[7], w1r1[7];
#pragma unroll
    for (int t = 0; t < 7; t++) {
        w1r0[t] = __ldg(w1 + t * 64 + c0);
        w1r1[t] = __ldg(w1 + t * 64 + c1);
    }
    const float lb10 = __ldg(b1 + c0), lb11 = __ldg(b1 + c1);
    const float lb20 = __ldg(b2 + c0), lb21 = __ldg(b2 + c1);

    float* ws = sm + D_SCR + warp * D_WS;
    const unsigned hidT32 =
        (unsigned)__cvta_generic_to_shared(sm) +
        (unsigned)(D_SCR + warp * D_WS) * 4u;

    const int gwarp = blockIdx.x * DW + warp;

#pragma unroll 1
    for (int p = gwarp; p < BB * NN; p += DWARPS) {
        const int b = p >> 12;
        const float qx = xyz[p * 3 + 0];
        const float qy = xyz[p * 3 + 1];
        const float qz = xyz[p * 3 + 2];
        const int2* kp = g_knn_pair + (size_t)p * KK;

        // ---- dfg layer 1: 4 k at a time, swizzled transpose store -------
        const int sA = (c0 >> 3) & 3;
#pragma unroll
        for (int kb = 0; kb < 4; kb++) {
            float2 hk[4];
#pragma unroll
            for (int kk = 0; kk < 4; kk++) {
                const int2 pr = kp[kb * 4 + kk];     // uniform broadcast LDG
                const int   j  = pr.x;
                const float dk = __int_as_float(pr.y);
                const float* nb = xyz + ((size_t)(b << 12) + j) * 3;
                const float g0 = nb[0], g1 = nb[1], g2 = nb[2];
                const float g3 = g0 - qx, g4 = g1 - qy, g5 = g2 - qz;
                float h0 = lb10, h1 = lb11;
                h0 = fmaf(g0, w1r0[0], h0); h1 = fmaf(g0, w1r1[0], h1);
                h0 = fmaf(g1, w1r0[1], h0); h1 = fmaf(g1, w1r1[1], h1);
                h0 = fmaf(g2, w1r0[2], h0); h1 = fmaf(g2, w1r1[2], h1);
                h0 = fmaf(g3, w1r0[3], h0); h1 = fmaf(g3, w1r1[3], h1);
                h0 = fmaf(g4, w1r0[4], h0); h1 = fmaf(g4, w1r1[4], h1);
                h0 = fmaf(g5, w1r0[5], h0); h1 = fmaf(g5, w1r1[5], h1);
                h0 = fmaf(dk, w1r0[6], h0); h1 = fmaf(dk, w1r1[6], h1);
                hk[kk] = make_float2(fmaxf(h0, 0.0f), fmaxf(h1, 0.0f));
            }
            const int slot = (kb ^ sA) << 2;
            *(float4*)(ws + c0 * 20 + slot) =
                make_float4(hk[0].x, hk[1].x, hk[2].x, hk[3].x);
            *(float4*)(ws + c1 * 20 + slot) =
                make_float4(hk[0].y, hk[1].y, hk[2].y, hk[3].y);
        }
        __syncwarp();

        // ---- dfg layer 2 + aggregation: two 8-k half-passes -------------
        float agg0 = 0.0f, agg1 = 0.0f;
#pragma unroll
        for (int ph = 0; ph < 2; ph++) {
            u64 a0[4], a1[4];
            {
                const u64 bb0 = f2pack(lb20, lb20);
                const u64 bb1 = f2pack(lb21, lb21);
#pragma unroll
                for (int m = 0; m < 4; m++) { a0[m] = bb0; a1[m] = bb1; }
            }
#pragma unroll
            for (int o = 0; o < 8; o++) {
#pragma unroll
                for (int tt = 0; tt < 8; tt++) {
                    const int t = o * 8 + tt;
                    const int sw = (t >> 3) & 3;
                    const float2 w = *(const float2*)&sm[D_W2 + t * 64 + c0];
                    const u64 w00 = f2pack(w.x, w.x);
                    const u64 w11 = f2pack(w.y, w.y);
                    const unsigned rowa = hidT32 + (unsigned)(t * 20) * 4u;
#pragma unroll
                    for (int g2 = 0; g2 < 2; g2++) {
                        const int g = ph * 2 + g2;
                        u64 h01, h23;
                        lds2x64(h01, h23,
                                rowa + (unsigned)(((g ^ sw) << 2) * 4));
                        const int m = g2 << 1;
                        a0[m]     = ffma2(h01, w00, a0[m]);
                        a0[m + 1] = ffma2(h23, w00, a0[m + 1]);
                        a1[m]     = ffma2(h01, w11, a1[m]);
                        a1[m + 1] = ffma2(h23, w11, a1[m + 1]);
                    }
                }
            }
            // aggregate this pass's 8 ks (k ascending overall)
#pragma unroll
            for (int m = 0; m < 4; m++) {
                float oE0, oO0, oE1, oO1;
                f2unpack(a0[m], oE0, oO0);
                f2unpack(a1[m], oE1, oO1);
#pragma unroll
                for (int kk = 0; kk < 2; kk++) {
                    const int k = ph * 8 + 2 * m + kk;
                    const float o0 = kk ? oO0 : oE0;
                    const float o1 = kk ? oO1 : oE1;
                    const int2 pr = kp[k];               // L1-hit broadcast
                    const int   j  = pr.x;
                    const float dk = __int_as_float(pr.y);
                    const float* nb = xyz + ((size_t)(b << 12) + j) * 3;
                    const float g0 = nb[0], g1 = nb[1], g2 = nb[2];
                    const float* prow = points + ((size_t)(b << 12) + j) * CPN;
                    float gp0 = (c0 >= 7) ? prow[c0 - 7] : 0.0f;
                    float gp1 = (c1 >= 7) ? prow[c1 - 7] : 0.0f;
                    if (lane == 0)      { gp0 = g0; gp1 = g1; }
                    else if (lane == 1) { gp0 = g2; gp1 = g0 - qx; }
                    else if (lane == 2) { gp0 = g1 - qy; gp1 = g2 - qz; }
                    else if (lane == 3) { gp0 = dk; }
                    agg0 = fmaf(o0, gp0, agg0);
                    agg1 = fmaf(o1, gp1, agg1);
                }
            }
        }
        agg0 *= 0.0625f; agg1 *= 0.0625f;

        float* hb = g_h67 + (size_t)p * 68;
        *(float2*)&hb[c0] = make_float2(agg0, agg1);
        if (lane == 0) { hb[64] = qx; hb[65] = qy; hb[66] = qz; }
        __syncwarp();
    }
}

// ============================================================================
// mlp kernel: PERSISTENT grid-stride (exact R12/R13 config).
// ============================================================================
#define MW       8
#define MPPW     4
#define MTPB     (MW * 32)
#define MBLOCKS  592
#define MWARPS   (MBLOCKS * MW)      // 4736
#define MGROUPS  (BB * NN / MPPW)    // 8192
#define M_WS     800
#define MSMEM_BYTES  (MW * M_WS * 4)

__global__ __launch_bounds__(MTPB)
void mlp_kernel(const float* __restrict__ points,
                const float* __restrict__ m1, const float* __restrict__ mb1,
                const float* __restrict__ m2, const float* __restrict__ mb2,
                const float* __restrict__ sc, const float* __restrict__ scb,
                float* __restrict__ out) {
    extern __shared__ float sm[];

    const int warp = threadIdx.x >> 5;
    const int lane = threadIdx.x & 31;
    const int c0 = 2 * lane;
    const int c4 = 4 * lane;

    float* h67b  = sm + warp * M_WS;   // 4 x 68, later reused as prow
    float* h128b = h67b + 272;         // 4 x 128

    const int gwarp = blockIdx.x * MW + warp;

#pragma unroll 1
    for (int grp = gwarp; grp < MGROUPS; grp += MWARPS) {
        const int pbase = grp * MPPW;

#pragma unroll
        for (int pp = 0; pp < MPPW; pp++) {
            const float* src = g_h67 + (size_t)(pbase + pp) * 68;
            for (int t = lane; t < 68; t += 32) h67b[pp * 68 + t] = src[t];
        }
        __syncwarp();

        // mlp1: [67] -> [128], relu.  input order = [xyz(3), agg(64)]
        {
            float a0[MPPW], a1[MPPW], a2[MPPW], a3[MPPW];
            const float4 bbv = __ldg((const float4*)(mb1 + c4));
#pragma unroll
            for (int pp = 0; pp < MPPW; pp++) {
                a0[pp] = bbv.x; a1[pp] = bbv.y; a2[pp] = bbv.z; a3[pp] = bbv.w;
            }

#pragma unroll
            for (int t = 0; t < 3; t++) {          // xyz rows
                const float4 w = __ldg((const float4*)(m1 + t * 128 + c4));
#pragma unroll
                for (int pp = 0; pp < MPPW; pp++) {
                    const float v = h67b[pp * 68 + 64 + t];
                    a0[pp] = fmaf(v, w.x, a0[pp]);
                    a1[pp] = fmaf(v, w.y, a1[pp]);
                    a2[pp] = fmaf(v, w.z, a2[pp]);
                    a3[pp] = fmaf(v, w.w, a3[pp]);
                }
            }
#pragma unroll 4
            for (int i = 0; i < 64; i++) {         // agg rows
                const float4 w = __ldg((const float4*)(m1 + (3 + i) * 128 + c4));
#pragma unroll
                for (int pp = 0; pp < MPPW; pp++) {
                    const float v = h67b[pp * 68 + i];
                    a0[pp] = fmaf(v, w.x, a0[pp]);
                    a1[pp] = fmaf(v, w.y, a1[pp]);
                    a2[pp] = fmaf(v, w.z, a2[pp]);
                    a3[pp] = fmaf(v, w.w, a3[pp]);
                }
            }
            __syncwarp();
#pragma unroll
            for (int pp = 0; pp < MPPW; pp++) {
                *(float4*)&h128b[pp * 128 + c4] =
                    make_float4(fmaxf(a0[pp], 0.0f), fmaxf(a1[pp], 0.0f),
                                fmaxf(a2[pp], 0.0f), fmaxf(a3[pp], 0.0f));
            }
        }
        __syncwarp();

        // reuse h67b as prow staging (mlp1 reads complete)
#pragma unroll
        for (int pp = 0; pp < MPPW; pp++) {
            const float* ps = points + (size_t)(pbase + pp) * CPN;
            for (int t = lane; t < CPN; t += 32) h67b[pp * 68 + t] = ps[t];
        }
        __syncwarp();

        // mlp2: [128] -> [64]
        float om0[MPPW], om1[MPPW];
        {
            const float2 mb = __ldg((const float2*)(mb2 + c0));
#pragma unroll
            for (int pp = 0; pp < MPPW; pp++) { om0[pp] = mb.x; om1[pp] = mb.y; }
#pragma unroll 4
            for (int t = 0; t < 128; t++) {
                const float2 w = __ldg((const float2*)(m2 + t * 64 + c0));
#pragma unroll
                for (int pp = 0; pp < MPPW; pp++) {
                    const float v = h128b[pp * 128 + t];
                    om0[pp] = fmaf(v, w.x, om0[pp]);
                    om1[pp] = fmaf(v, w.y, om1[pp]);
                }
            }
        }

        // shortcut: points @ sc_w + sc_b
        float or0[MPPW], or1[MPPW];
        {
            const float2 sb = __ldg((const float2*)(scb + c0));
#pragma unroll
            for (int pp = 0; pp < MPPW; pp++) { or0[pp] = sb.x; or1[pp] = sb.y; }
#pragma unroll 4
            for (int t = 0; t < CPN; t++) {
                const float2 w = __ldg((const float2*)(sc + t * 64 + c0));
#pragma unroll
                for (int pp = 0; pp < MPPW; pp++) {
                    const float v = h67b[pp * 68 + t];
                    or0[pp] = fmaf(v, w.x, or0[pp]);
                    or1[pp] = fmaf(v, w.y, or1[pp]);
                }
            }
        }

#pragma unroll
        for (int pp = 0; pp < MPPW; pp++) {
            const int p = pbase + pp;
            *(float2*)&out[(size_t)p * 64 + c0] =
                make_float2(fmaxf(or0[pp] + om0[pp], 0.0f),
                            fmaxf(or1[pp] + om1[pp], 0.0f));
        }
        __syncwarp();
    }
}

// ============================================================================
extern "C" void kernel_launch(void* const* d_in, const int* in_sizes, int n_in,
                              void* d_out, int out_size) {
    const float* xyz    = (const float*)d_in[0];
    const float* points = (const float*)d_in[1];
    const float* w1     = (const float*)d_in[2];
    const float* b1     = (const float*)d_in[3];
    const float* w2     = (const float*)d_in[4];
    const float* b2     = (const float*)d_in[5];
    const float* m1     = (const float*)d_in[6];
    const float* mb1    = (const float*)d_in[7];
    const float* m2     = (const float*)d_in[8];
    const float* mb2    = (const float*)d_in[9];
    const float* sc     = (const float*)d_in[10];
    const float* scb    = (const float*)d_in[11];
    float* out = (float*)d_out;
    (void)in_sizes; (void)n_in; (void)out_size;

    grid_build<<<BB, 512>>>(xyz);
    knn_query<<<dim3(NN / 64, BB), 128>>>();

    cudaFuncSetAttribute(dfg_kernel,
                         cudaFuncAttributeMaxDynamicSharedMemorySize,
                         DSMEM_BYTES);
    dfg_kernel<<<DBLOCKS, DTPB, DSMEM_BYTES>>>(
        xyz, points, w1, b1, w2, b2);

    cudaFuncSetAttribute(mlp_kernel,
                         cudaFuncAttributeMaxDynamicSharedMemorySize,
                         MSMEM_BYTES);
    mlp_kernel<<<MBLOCKS, MTPB, MSMEM_BYTES>>>(
        points, m1, mb1, m2, mb2, sc, scb, out);
}

// round 16
// speedup vs baseline: 1.3311x; 1.1229x over previous
#include <cuda_runtime.h>
#include <stdint.h>

#define BB   8
#define NN   4096
#define CPN  57
#define KK   16
#define THR  0.04f
#define GD   10          // cells per dim
#define NC2  1000        // GD^3
#define NBIN 64
#define THCAP 8          // per-thread threshold-list slots (4 threads/point)

// ---------------- scratch (device globals; no allocation allowed) -----------
__device__ int2   g_knn_pair[BB * NN * KK];   // (idx, dist bits) interleaved
__device__ int    g_off[BB * 1024];
__device__ float4 g_sx[BB * NN];
__device__ int    g_sj[BB * NN];
__device__ float  g_h67[BB * NN * 68];        // [agg(64) | xyz(3) | pad]

// ---------------------------------------------------------------------------
// f32x2 packed helpers
// ---------------------------------------------------------------------------
typedef unsigned long long u64;
__device__ __forceinline__ u64 f2pack(float a, float b) {
    u64 r; asm("mov.b64 %0,{%1,%2};" : "=l"(r) : "f"(a), "f"(b)); return r;
}
__device__ __forceinline__ void f2unpack(u64 v, float& a, float& b) {
    asm("mov.b64 {%0,%1},%2;" : "=f"(a), "=f"(b) : "l"(v));
}
__device__ __forceinline__ u64 ffma2(u64 a, u64 b, u64 c) {
    u64 d; asm("fma.rn.f32x2 %0,%1,%2,%3;" : "=l"(d) : "l"(a), "l"(b), "l"(c));
    return d;
}
__device__ __forceinline__ void lds2x64(u64& a, u64& b, unsigned addr) {
    asm volatile("ld.shared.v2.b64 {%0,%1},[%2];"
                 : "=l"(a), "=l"(b) : "r"(addr));
}

// ---------------------------------------------------------------------------
// Fused grid build: one block per batch, 10^3 cells (cell = radius/2 = 0.1).
// ---------------------------------------------------------------------------
__device__ __forceinline__ int cell_of(float x, float y, float z) {
    int cx = min((int)(x * 10.0f), GD - 1);
    int cy = min((int)(y * 10.0f), GD - 1);
    int cz = min((int)(z * 10.0f), GD - 1);
    return (cx * GD + cy) * GD + cz;
}

__global__ void grid_build(const float* __restrict__ xyz) {
    __shared__ int scnt[1024];
    __shared__ int ssum[512];
    __shared__ int soff[1024 + 1];
    __shared__ int scur[1024];
    const int tid = threadIdx.x;
    const int b = blockIdx.x;
    const float* bx = xyz + (size_t)b * NN * 3;

    scnt[tid] = 0; scnt[tid + 512] = 0;
    __syncthreads();

    for (int i = tid; i < NN; i += 512) {
        float x = bx[i * 3 + 0], y = bx[i * 3 + 1], z = bx[i * 3 + 2];
        atomicAdd(&scnt[cell_of(x, y, z)], 1);
    }
    __syncthreads();

    const int c0v = scnt[2 * tid];
    const int c1v = scnt[2 * tid + 1];
    ssum[tid] = c0v + c1v;
    __syncthreads();
#pragma unroll
    for (int d = 1; d < 512; d <<= 1) {
        int v = ssum[tid];
        int u = (tid >= d) ? ssum[tid - d] : 0;
        __syncthreads();
        ssum[tid] = v + u;
        __syncthreads();
    }
    const int excl = (tid == 0) ? 0 : ssum[tid - 1];
    soff[2 * tid]     = excl;
    soff[2 * tid + 1] = excl + c0v;
    scur[2 * tid]     = excl;
    scur[2 * tid + 1] = excl + c0v;
    if (tid == 511) soff[1024] = ssum[511];
    __syncthreads();

    for (int t = tid; t <= NC2; t += 512) g_off[b * 1024 + t] = soff[t];

    for (int i = tid; i < NN; i += 512) {
        float x = bx[i * 3 + 0], y = bx[i * 3 + 1], z = bx[i * 3 + 2];
        int cell = cell_of(x, y, z);
        int pos = atomicAdd(&scur[cell], 1);
        float sq = fmaf(z, z, fmaf(y, y, x * x));
        g_sx[(b << 12) + pos] = make_float4(x, y, z, sq);
        g_sj[(b << 12) + pos] = i;
    }
}

// ---------------------------------------------------------------------------
// kNN query: FOUR threads per point.  25 (dx,dy) cell columns split
// {7,6,6,6}; deterministic merge via pass-A histograms (no atomics):
// thread h's direct-stream base = sum of counts of columns < h in bins
// < t*; threshold bin resolved by quad-lane0 over 4 fixed sub-lists with
// exact (d, j)-lexicographic order.  Selected SET identical to 1-thread
// version; only within-list order permutes.
// ---------------------------------------------------------------------------
#define KNN_SCAN2(MLO, MHI, BODY)                                             \
    for (int m = (MLO); m < (MHI); m++) {                                     \
        const int dx = m / 5 - 2, dy = m % 5 - 2;                             \
        int ncx = cx + dx; if (ncx < 0 || ncx > GD - 1) continue;             \
        int ncy = cy + dy; if (ncy < 0 || ncy > GD - 1) continue;             \
        int cb2 = b * 1024 + (ncx * GD + ncy) * GD;                           \
        int sbeg = g_off[cb2 + czlo];                                         \
        int send = g_off[cb2 + czhi + 1];                                     \
        for (int s = sbeg; s < send; s++) {                                   \
            float4 c = g_sx[(b << 12) + s];                                   \
            float dot = fmaf(q.z, c.z, fmaf(q.y, c.y, q.x * c.x));            \
            float rhs = fmaf(0.5f, c.w, qoff);                                \
            if (dot >= rhs) {                                                 \
                float t1 = qsq + c.w;                                         \
                float d = __fsub_rn(t1, __fmul_rn(2.0f, dot));                \
                if (d <= THR) { BODY }                                        \
            }                                                                 \
        }                                                                     \
    }

__global__ __launch_bounds__(128) void knn_query() {
    __shared__ unsigned short hist[NBIN * 128];   // 16KB, column per thread
    __shared__ int2 tl[32 * 4 * THCAP];           // 8KB
    const int tid  = threadIdx.x;
    const int pt   = tid >> 2;                    // local point 0..31
    const int quad = tid & 3;                     // which quarter of columns
    const int b    = blockIdx.y;
    const int slot = blockIdx.x * 32 + pt;
    const float4 q = g_sx[(b << 12) + slot];
    const int qi   = g_sj[(b << 12) + slot];
    const float qsq = q.w;
    const int cx = min((int)(q.x * 10.0f), GD - 1);
    const int cy = min((int)(q.y * 10.0f), GD - 1);
    const int cz = min((int)(q.z * 10.0f), GD - 1);
    const float qoff = 0.5f * (qsq - THR) - 1e-5f;
    const int czlo = max(cz - 2, 0), czhi = min(cz + 2, GD - 1);
    // column split {7,6,6,6}
    const int mlo = (quad == 0) ? 0 : (quad == 1) ? 7 : (quad == 2) ? 13 : 19;
    const int mhi = (quad == 0) ? 7 : (quad == 1) ? 13 : (quad == 2) ? 19 : 25;

#pragma unroll 8
    for (int bn = 0; bn < NBIN; bn++) hist[bn * 128 + tid] = 0;

    // ---- pass A: histogram of exact d (my quarter of cell columns) ------
    KNN_SCAN2(mlo, mhi, {
        int bn = max(0, min(NBIN - 1, (int)(d * 1600.0f)));   // 64 / 0.04
        hist[bn * 128 + tid]++;
    })
    __syncwarp();

    // ---- combined threshold + my direct-stream base ----------------------
    const int colb = tid & ~3;
    int tstar = NBIN, cum = 0, ndpre = 0, ndt = 0;
#pragma unroll 8
    for (int bn = 0; bn < NBIN; bn++) {
        const int h0 = (int)hist[bn * 128 + colb + 0];
        const int h1 = (int)hist[bn * 128 + colb + 1];
        const int h2 = (int)hist[bn * 128 + colb + 2];
        const int h3 = (int)hist[bn * 128 + colb + 3];
        const int c = h0 + h1 + h2 + h3;
        if (tstar == NBIN && cum + c >= KK) tstar = bn;
        if (tstar == NBIN) {                  // bins strictly below t*
            ndt += c;
            ndpre += (quad > 0 ? h0 : 0) + (quad > 1 ? h1 : 0)
                   + (quad > 2 ? h2 : 0);
        }
        cum += c;
    }

    const int base = (b * NN + qi) * KK;
    int cnt = 0, tcnt = 0;

    // ---- pass B: direct-stream (deterministic offsets) + threshold list --
    KNN_SCAN2(mlo, mhi, {
        int bn = max(0, min(NBIN - 1, (int)(d * 1600.0f)));
        if (bn < tstar) {
            int j = g_sj[(b << 12) + s];
            g_knn_pair[base + ndpre + cnt] =
                make_int2(j, __float_as_int(fmaxf(d, 0.0f)));
            cnt++;
        } else if (bn == tstar && tcnt < THCAP) {
            int j = g_sj[(b << 12) + s];
            tl[(pt * 4 + quad) * THCAP + tcnt] = make_int2(j, __float_as_int(d));
            tcnt++;
        }
    })
    __syncwarp();

    // ---- resolve threshold bin + padding (quad-lane 0) -------------------
    if (quad == 0) {
        int wcnt = ndt;                       // direct entries fill [0, ndt)
        if (tstar < NBIN) {
            int tc[4];
#pragma unroll
            for (int j2 = 0; j2 < 4; j2++)
                tc[j2] = min((int)hist[tstar * 128 + colb + j2], THCAP);
            int need = KK - ndt;
            const int tot = tc[0] + tc[1] + tc[2] + tc[3];
            if (need > tot) need = tot;
            const int tb = pt * 4 * THCAP;
            for (int s2 = 0; s2 < need; s2++) {
                float bd = 3.0e38f; int bj = 0x7fffffff, bi = -1;
#pragma unroll
                for (int j2 = 0; j2 < 4; j2++) {
                    for (int i2 = 0; i2 < tc[j2]; i2++) {
                        int2 e = tl[tb + j2 * THCAP + i2];
                        float dv = __int_as_float(e.y);
                        bool g = (dv < bd) || (dv == bd && e.x < bj);
                        if (g) { bd = dv; bj = e.x; bi = tb + j2 * THCAP + i2; }
                    }
                }
                tl[bi].y = __float_as_int(3.0e38f);
                g_knn_pair[base + wcnt] =
                    make_int2(bj, __float_as_int(fmaxf(bd, 0.0f)));
                wcnt++;
            }
        }
        for (; wcnt < KK; wcnt++) g_knn_pair[base + wcnt] = make_int2(qi, 0);
    }
}

// ============================================================================
// dfg kernel v4 (exact R15 config): half-pass accumulators + W2 in SMEM,
// W1/b via __ldg, 6 blocks/SM target, persistent 888 blocks.
// ============================================================================
#define DW       4
#define DTPB     (DW * 32)
#define DBLOCKS  (6 * 148)           // 888
#define DWARPS   (DBLOCKS * DW)      // 3552
#define D_W2     0
#define D_SCR    4160                // 4096 W2 + 64 pad
#define D_WS     1296
#define DSMEM_FLOATS (D_SCR + DW * D_WS)   // 9344
#define DSMEM_BYTES  (DSMEM_FLOATS * 4)    // 37376

__global__ __launch_bounds__(DTPB, 6)
void dfg_kernel(const float* __restrict__ xyz,
                const float* __restrict__ points,
                const float* __restrict__ w1, const float* __restrict__ b1,
                const float* __restrict__ w2, const float* __restrict__ b2) {
    extern __shared__ float sm[];

    for (int t = threadIdx.x; t < 4096; t += DTPB) sm[D_W2 + t] = w2[t];
    __syncthreads();

    const int warp = threadIdx.x >> 5;
    const int lane = threadIdx.x & 31;
    const int c0 = 2 * lane, c1 = c0 + 1;

    float w1r0[7], w1r1[7];
#pragma unroll
    for (int t = 0; t < 7; t++) {
        w1r0[t] = __ldg(w1 + t * 64 + c0);
        w1r1[t] = __ldg(w1 + t * 64 + c1);
    }
    const float lb10 = __ldg(b1 + c0), lb11 = __ldg(b1 + c1);
    const float lb20 = __ldg(b2 + c0), lb21 = __ldg(b2 + c1);

    float* ws = sm + D_SCR + warp * D_WS;
    const unsigned hidT32 =
        (unsigned)__cvta_generic_to_shared(sm) +
        (unsigned)(D_SCR + warp * D_WS) * 4u;

    const int gwarp = blockIdx.x * DW + warp;

#pragma unroll 1
    for (int p = gwarp; p < BB * NN; p += DWARPS) {
        const int b = p >> 12;
        const float qx = xyz[p * 3 + 0];
        const float qy = xyz[p * 3 + 1];
        const float qz = xyz[p * 3 + 2];
        const int2* kp = g_knn_pair + (size_t)p * KK;

        // ---- dfg layer 1: 4 k at a time, swizzled transpose store -------
        const int sA = (c0 >> 3) & 3;
#pragma unroll
        for (int kb = 0; kb < 4; kb++) {
            float2 hk[4];
#pragma unroll
            for (int kk = 0; kk < 4; kk++) {
                const int2 pr = kp[kb * 4 + kk];     // uniform broadcast LDG
                const int   j  = pr.x;
                const float dk = __int_as_float(pr.y);
                const float* nb = xyz + ((size_t)(b << 12) + j) * 3;
                const float g0 = nb[0], g1 = nb[1], g2 = nb[2];
                const float g3 = g0 - qx, g4 = g1 - qy, g5 = g2 - qz;
                float h0 = lb10, h1 = lb11;
                h0 = fmaf(g0, w1r0[0], h0); h1 = fmaf(g0, w1r1[0], h1);
                h0 = fmaf(g1, w1r0[1], h0); h1 = fmaf(g1, w1r1[1], h1);
                h0 = fmaf(g2, w1r0[2], h0); h1 = fmaf(g2, w1r1[2], h1);
                h0 = fmaf(g3, w1r0[3], h0); h1 = fmaf(g3, w1r1[3], h1);
                h0 = fmaf(g4, w1r0[4], h0); h1 = fmaf(g4, w1r1[4], h1);
                h0 = fmaf(g5, w1r0[5], h0); h1 = fmaf(g5, w1r1[5], h1);
                h0 = fmaf(dk, w1r0[6], h0); h1 = fmaf(dk, w1r1[6], h1);
                hk[kk] = make_float2(fmaxf(h0, 0.0f), fmaxf(h1, 0.0f));
            }
            const int slot = (kb ^ sA) << 2;
            *(float4*)(ws + c0 * 20 + slot) =
                make_float4(hk[0].x, hk[1].x, hk[2].x, hk[3].x);
            *(float4*)(ws + c1 * 20 + slot) =
                make_float4(hk[0].y, hk[1].y, hk[2].y, hk[3].y);
        }
        __syncwarp();

        // ---- dfg layer 2 + aggregation: two 8-k half-passes -------------
        float agg0 = 0.0f, agg1 = 0.0f;
#pragma unroll
        for (int ph = 0; ph < 2; ph++) {
            u64 a0[4], a1[4];
            {
                const u64 bb0 = f2pack(lb20, lb20);
                const u64 bb1 = f2pack(lb21, lb21);
#pragma unroll
                for (int m = 0; m < 4; m++) { a0[m] = bb0; a1[m] = bb1; }
            }
#pragma unroll
            for (int o = 0; o < 8; o++) {
#pragma unroll
                for (int tt = 0; tt < 8; tt++) {
                    const int t = o * 8 + tt;
                    const int sw = (t >> 3) & 3;
                    const float2 w = *(const float2*)&sm[D_W2 + t * 64 + c0];
                    const u64 w00 = f2pack(w.x, w.x);
                    const u64 w11 = f2pack(w.y, w.y);
                    const unsigned rowa = hidT32 + (unsigned)(t * 20) * 4u;
#pragma unroll
                    for (int g2 = 0; g2 < 2; g2++) {
                        const int g = ph * 2 + g2;
                        u64 h01, h23;
                        lds2x64(h01, h23,
                                rowa + (unsigned)(((g ^ sw) << 2) * 4));
                        const int m = g2 << 1;
                        a0[m]     = ffma2(h01, w00, a0[m]);
                        a0[m + 1] = ffma2(h23, w00, a0[m + 1]);
                        a1[m]     = ffma2(h01, w11, a1[m]);
                        a1[m + 1] = ffma2(h23, w11, a1[m + 1]);
                    }
                }
            }
            // aggregate this pass's 8 ks (k ascending overall)
#pragma unroll
            for (int m = 0; m < 4; m++) {
                float oE0, oO0, oE1, oO1;
                f2unpack(a0[m], oE0, oO0);
                f2unpack(a1[m], oE1, oO1);
#pragma unroll
                for (int kk = 0; kk < 2; kk++) {
                    const int k = ph * 8 + 2 * m + kk;
                    const float o0 = kk ? oO0 : oE0;
                    const float o1 = kk ? oO1 : oE1;
                    const int2 pr = kp[k];               // L1-hit broadcast
                    const int   j  = pr.x;
                    const float dk = __int_as_float(pr.y);
                    const float* nb = xyz + ((size_t)(b << 12) + j) * 3;
                    const float g0 = nb[0], g1 = nb[1], g2 = nb[2];
                    const float* prow = points + ((size_t)(b << 12) + j) * CPN;
                    float gp0 = (c0 >= 7) ? prow[c0 - 7] : 0.0f;
                    float gp1 = (c1 >= 7) ? prow[c1 - 7] : 0.0f;
                    if (lane == 0)      { gp0 = g0; gp1 = g1; }
                    else if (lane == 1) { gp0 = g2; gp1 = g0 - qx; }
                    else if (lane == 2) { gp0 = g1 - qy; gp1 = g2 - qz; }
                    else if (lane == 3) { gp0 = dk; }
                    agg0 = fmaf(o0, gp0, agg0);
                    agg1 = fmaf(o1, gp1, agg1);
                }
            }
        }
        agg0 *= 0.0625f; agg1 *= 0.0625f;

        float* hb = g_h67 + (size_t)p * 68;
        *(float2*)&hb[c0] = make_float2(agg0, agg1);
        if (lane == 0) { hb[64] = qx; hb[65] = qy; hb[66] = qz; }
        __syncwarp();
    }
}

// ============================================================================
// mlp kernel: PERSISTENT grid-stride (exact R12/R13 config).
// ============================================================================
#define MW       8
#define MPPW     4
#define MTPB     (MW * 32)
#define MBLOCKS  592
#define MWARPS   (MBLOCKS * MW)      // 4736
#define MGROUPS  (BB * NN / MPPW)    // 8192
#define M_WS     800
#define MSMEM_BYTES  (MW * M_WS * 4)

__global__ __launch_bounds__(MTPB)
void mlp_kernel(const float* __restrict__ points,
                const float* __restrict__ m1, const float* __restrict__ mb1,
                const float* __restrict__ m2, const float* __restrict__ mb2,
                const float* __restrict__ sc, const float* __restrict__ scb,
                float* __restrict__ out) {
    extern __shared__ float sm[];

    const int warp = threadIdx.x >> 5;
    const int lane = threadIdx.x & 31;
    const int c0 = 2 * lane;
    const int c4 = 4 * lane;

    float* h67b  = sm + warp * M_WS;   // 4 x 68, later reused as prow
    float* h128b = h67b + 272;         // 4 x 128

    const int gwarp = blockIdx.x * MW + warp;

#pragma unroll 1
    for (int grp = gwarp; grp < MGROUPS; grp += MWARPS) {
        const int pbase = grp * MPPW;

#pragma unroll
        for (int pp = 0; pp < MPPW; pp++) {
            const float* src = g_h67 + (size_t)(pbase + pp) * 68;
            for (int t = lane; t < 68; t += 32) h67b[pp * 68 + t] = src[t];
        }
        __syncwarp();

        // mlp1: [67] -> [128], relu.  input order = [xyz(3), agg(64)]
        {
            float a0[MPPW], a1[MPPW], a2[MPPW], a3[MPPW];
            const float4 bbv = __ldg((const float4*)(mb1 + c4));
#pragma unroll
            for (int pp = 0; pp < MPPW; pp++) {
                a0[pp] = bbv.x; a1[pp] = bbv.y; a2[pp] = bbv.z; a3[pp] = bbv.w;
            }

#pragma unroll
            for (int t = 0; t < 3; t++) {          // xyz rows
                const float4 w = __ldg((const float4*)(m1 + t * 128 + c4));
#pragma unroll
                for (int pp = 0; pp < MPPW; pp++) {
                    const float v = h67b[pp * 68 + 64 + t];
                    a0[pp] = fmaf(v, w.x, a0[pp]);
                    a1[pp] = fmaf(v, w.y, a1[pp]);
                    a2[pp] = fmaf(v, w.z, a2[pp]);
                    a3[pp] = fmaf(v, w.w, a3[pp]);
                }
            }
#pragma unroll 4
            for (int i = 0; i < 64; i++) {         // agg rows
                const float4 w = __ldg((const float4*)(m1 + (3 + i) * 128 + c4));
#pragma unroll
                for (int pp = 0; pp < MPPW; pp++) {
                    const float v = h67b[pp * 68 + i];
                    a0[pp] = fmaf(v, w.x, a0[pp]);
                    a1[pp] = fmaf(v, w.y, a1[pp]);
                    a2[pp] = fmaf(v, w.z, a2[pp]);
                    a3[pp] = fmaf(v, w.w, a3[pp]);
                }
            }
            __syncwarp();
#pragma unroll
            for (int pp = 0; pp < MPPW; pp++) {
                *(float4*)&h128b[pp * 128 + c4] =
                    make_float4(fmaxf(a0[pp], 0.0f), fmaxf(a1[pp], 0.0f),
                                fmaxf(a2[pp], 0.0f), fmaxf(a3[pp], 0.0f));
            }
        }
        __syncwarp();

        // reuse h67b as prow staging (mlp1 reads complete)
#pragma unroll
        for (int pp = 0; pp < MPPW; pp++) {
            const float* ps = points + (size_t)(pbase + pp) * CPN;
            for (int t = lane; t < CPN; t += 32) h67b[pp * 68 + t] = ps[t];
        }
        __syncwarp();

        // mlp2: [128] -> [64]
        float om0[MPPW], om1[MPPW];
        {
            const float2 mb = __ldg((const float2*)(mb2 + c0));
#pragma unroll
            for (int pp = 0; pp < MPPW; pp++) { om0[pp] = mb.x; om1[pp] = mb.y; }
#pragma unroll 4
            for (int t = 0; t < 128; t++) {
                const float2 w = __ldg((const float2*)(m2 + t * 64 + c0));
#pragma unroll
                for (int pp = 0; pp < MPPW; pp++) {
                    const float v = h128b[pp * 128 + t];
                    om0[pp] = fmaf(v, w.x, om0[pp]);
                    om1[pp] = fmaf(v, w.y, om1[pp]);
                }
            }
        }

        // shortcut: points @ sc_w + sc_b
        float or0[MPPW], or1[MPPW];
        {
            const float2 sb = __ldg((const float2*)(scb + c0));
#pragma unroll
            for (int pp = 0; pp < MPPW; pp++) { or0[pp] = sb.x; or1[pp] = sb.y; }
#pragma unroll 4
            for (int t = 0; t < CPN; t++) {
                const float2 w = __ldg((const float2*)(sc + t * 64 + c0));
#pragma unroll
                for (int pp = 0; pp < MPPW; pp++) {
                    const float v = h67b[pp * 68 + t];
                    or0[pp] = fmaf(v, w.x, or0[pp]);
                    or1[pp] = fmaf(v, w.y, or1[pp]);
                }
            }
        }

#pragma unroll
        for (int pp = 0; pp < MPPW; pp++) {
            const int p = pbase + pp;
            *(float2*)&out[(size_t)p * 64 + c0] =
                make_float2(fmaxf(or0[pp] + om0[pp], 0.0f),
                            fmaxf(or1[pp] + om1[pp], 0.0f));
        }
        __syncwarp();
    }
}

// ============================================================================
extern "C" void kernel_launch(void* const* d_in, const int* in_sizes, int n_in,
                              void* d_out, int out_size) {
    const float* xyz    = (const float*)d_in[0];
    const float* points = (const float*)d_in[1];
    const float* w1     = (const float*)d_in[2];
    const float* b1     = (const float*)d_in[3];
    const float* w2     = (const float*)d_in[4];
    const float* b2     = (const float*)d_in[5];
    const float* m1     = (const float*)d_in[6];
    const float* mb1    = (const float*)d_in[7];
    const float* m2     = (const float*)d_in[8];
    const float* mb2    = (const float*)d_in[9];
    const float* sc     = (const float*)d_in[10];
    const float* scb    = (const float*)d_in[11];
    float* out = (float*)d_out;
    (void)in_sizes; (void)n_in; (void)out_size;

    grid_build<<<BB, 512>>>(xyz);
    knn_query<<<dim3(NN / 32, BB), 128>>>();

    cudaFuncSetAttribute(dfg_kernel,
                         cudaFuncAttributeMaxDynamicSharedMemorySize,
                         DSMEM_BYTES);
    dfg_kernel<<<DBLOCKS, DTPB, DSMEM_BYTES>>>(
        xyz, points, w1, b1, w2, b2);

    cudaFuncSetAttribute(mlp_kernel,
                         cudaFuncAttributeMaxDynamicSharedMemorySize,
                         MSMEM_BYTES);
    mlp_kernel<<<MBLOCKS, MTPB, MSMEM_BYTES>>>(
        points, m1, mb1, m2, mb2, sc, scb, out);
}